// round 1
// baseline (speedup 1.0000x reference)
#include <cuda_runtime.h>

#define B_ROWS 131072
#define D_DIM 128
#define G_NUM 128
#define CHUNKS 8

// Scratch in __device__ globals (no allocation allowed). Counters padded to
// 128 B apart so contended atomics spread across LTS slices.
__device__ int   g_counts[G_NUM * 32];
__device__ int   g_cursor[G_NUM * 32];
__device__ int   g_offsets[G_NUM + 1];
__device__ int   g_bucket[B_ROWS];
__device__ float g_csum[G_NUM * D_DIM];
__device__ float g_dsum[G_NUM * 32];

__global__ void k_zero() {
    int i = blockIdx.x * blockDim.x + threadIdx.x;
    if (i < G_NUM * 32) { g_counts[i] = 0; g_dsum[i] = 0.0f; }
    if (i < G_NUM * D_DIM) g_csum[i] = 0.0f;
}

__global__ void k_hist(const int* __restrict__ subject, const int* __restrict__ labels) {
    int i = blockIdx.x * blockDim.x + threadIdx.x;
    if (i < B_ROWS) {
        int g = subject[i] * 8 + labels[i];
        atomicAdd(&g_counts[g * 32], 1);
    }
}

__global__ void k_scan() {
    if (threadIdx.x == 0) {
        int acc = 0;
        for (int g = 0; g < G_NUM; g++) {
            g_offsets[g] = acc;
            g_cursor[g * 32] = acc;
            acc += g_counts[g * 32];
        }
        g_offsets[G_NUM] = acc;
    }
}

__global__ void k_scatter(const int* __restrict__ subject, const int* __restrict__ labels) {
    int i = blockIdx.x * blockDim.x + threadIdx.x;
    if (i < B_ROWS) {
        int g = subject[i] * 8 + labels[i];
        int pos = atomicAdd(&g_cursor[g * 32], 1);
        g_bucket[pos] = i;
    }
}

// Block per (group, chunk). 256 threads cover one row's 256 floats
// (both views, 1 KB contiguous). Unroll-4 over rows for MLP.
__global__ void k_centroid(const float* __restrict__ X) {
    int g = blockIdx.x >> 3, chunk = blockIdx.x & 7;
    int s0 = g_offsets[g], s1 = g_offsets[g + 1], n = s1 - s0;
    int cs = s0 + (n * chunk) / CHUNKS;
    int ce = s0 + (n * (chunk + 1)) / CHUNKS;
    int t = threadIdx.x;

    float acc = 0.0f;
    int r = cs;
    for (; r + 4 <= ce; r += 4) {
        int b0 = g_bucket[r], b1 = g_bucket[r + 1];
        int b2 = g_bucket[r + 2], b3 = g_bucket[r + 3];
        float x0 = X[(size_t)b0 * 256 + t];
        float x1 = X[(size_t)b1 * 256 + t];
        float x2 = X[(size_t)b2 * 256 + t];
        float x3 = X[(size_t)b3 * 256 + t];
        acc += (x0 + x1) + (x2 + x3);
    }
    for (; r < ce; r++) acc += X[(size_t)g_bucket[r] * 256 + t];

    __shared__ float s_acc[256];
    s_acc[t] = acc;
    __syncthreads();
    if (t < 128) atomicAdd(&g_csum[g * 128 + t], s_acc[t] + s_acc[t + 128]);
}

// Warp per (row, view): lane l holds float4 of centroid dims 4l..4l+3.
// Butterfly reduce the squared distance, accumulate sqrt(sqrt(d2)).
__global__ void k_dist(const float* __restrict__ X) {
    int g = blockIdx.x >> 3, chunk = blockIdx.x & 7;
    __shared__ float c[128];
    int t = threadIdx.x;
    float cnt2 = 2.0f * (float)g_counts[g * 32];
    if (t < 128) c[t] = g_csum[g * 128 + t] / cnt2;
    __syncthreads();

    int w = t >> 5, l = t & 31;
    float4 c4 = ((const float4*)c)[l];
    int s0 = g_offsets[g], s1 = g_offsets[g + 1], n = s1 - s0;
    int cs = s0 + (n * chunk) / CHUNKS;
    int ce = s0 + (n * (chunk + 1)) / CHUNKS;

    float s = 0.0f;
    int r = cs + w;
    while (r + 8 < ce) {
        int ba = g_bucket[r];
        int bb = g_bucket[r + 8];
        const float4* pa = (const float4*)(X + (size_t)ba * 256);
        const float4* pb = (const float4*)(X + (size_t)bb * 256);
        float4 a0 = pa[l], a1 = pa[l + 32];
        float4 b0 = pb[l], b1 = pb[l + 32];
        float dx, dy, dz, dw;
        dx = a0.x - c4.x; dy = a0.y - c4.y; dz = a0.z - c4.z; dw = a0.w - c4.w;
        float d0 = dx * dx + dy * dy + dz * dz + dw * dw;
        dx = a1.x - c4.x; dy = a1.y - c4.y; dz = a1.z - c4.z; dw = a1.w - c4.w;
        float d1 = dx * dx + dy * dy + dz * dz + dw * dw;
        dx = b0.x - c4.x; dy = b0.y - c4.y; dz = b0.z - c4.z; dw = b0.w - c4.w;
        float d2 = dx * dx + dy * dy + dz * dz + dw * dw;
        dx = b1.x - c4.x; dy = b1.y - c4.y; dz = b1.z - c4.z; dw = b1.w - c4.w;
        float d3 = dx * dx + dy * dy + dz * dz + dw * dw;
        #pragma unroll
        for (int o = 16; o; o >>= 1) {
            d0 += __shfl_xor_sync(0xffffffff, d0, o);
            d1 += __shfl_xor_sync(0xffffffff, d1, o);
            d2 += __shfl_xor_sync(0xffffffff, d2, o);
            d3 += __shfl_xor_sync(0xffffffff, d3, o);
        }
        s += (sqrtf(sqrtf(d0)) + sqrtf(sqrtf(d1))) + (sqrtf(sqrtf(d2)) + sqrtf(sqrtf(d3)));
        r += 16;
    }
    if (r < ce) {
        int b = g_bucket[r];
        const float4* px = (const float4*)(X + (size_t)b * 256);
        float4 x0 = px[l], x1 = px[l + 32];
        float dx, dy, dz, dw;
        dx = x0.x - c4.x; dy = x0.y - c4.y; dz = x0.z - c4.z; dw = x0.w - c4.w;
        float d0 = dx * dx + dy * dy + dz * dz + dw * dw;
        dx = x1.x - c4.x; dy = x1.y - c4.y; dz = x1.z - c4.z; dw = x1.w - c4.w;
        float d1 = dx * dx + dy * dy + dz * dz + dw * dw;
        #pragma unroll
        for (int o = 16; o; o >>= 1) {
            d0 += __shfl_xor_sync(0xffffffff, d0, o);
            d1 += __shfl_xor_sync(0xffffffff, d1, o);
        }
        s += sqrtf(sqrtf(d0)) + sqrtf(sqrtf(d1));
    }
    if (l == 0 && s != 0.0f) atomicAdd(&g_dsum[g * 32], s);
    else if (l == 0) atomicAdd(&g_dsum[g * 32], s);  // keep deterministic: always add
}

// Single block, 128 threads: dens, percentile (linear interp like
// jnp.percentile), clip, normalize, centroid-of-centroids, exp/max/mean.
__global__ void k_final(float* __restrict__ out) {
    int g = threadIdx.x;
    __shared__ float sd[128], ss[128], scnt[128], scoc[128];
    __shared__ float red;

    float cnt2 = 2.0f * (float)g_counts[g * 32];
    scnt[g] = cnt2;
    float dens = (g_dsum[g * 32] / cnt2) / logf(cnt2 + 10.0f);
    bool valid = cnt2 > 1.0f;
    sd[g] = valid ? dens : 0.0f;
    __syncthreads();
    if (g == 0) {
        float m = sd[0];
        for (int i = 1; i < 128; i++) m = fmaxf(m, sd[i]);
        red = m;
    }
    __syncthreads();
    dens = valid ? dens : red;

    // sorted order via stable rank counting (ties broken by index)
    sd[g] = dens;
    __syncthreads();
    int rank = 0;
    for (int j = 0; j < 128; j++) {
        float v = sd[j];
        rank += (v < dens) || (v == dens && j < g);
    }
    ss[rank] = dens;
    __syncthreads();
    // percentile positions: 0.1*127 = 12.7 ; 0.9*127 = 114.3
    float lo = ss[12] + 0.7f * (ss[13] - ss[12]);
    float hi = ss[114] + 0.3f * (ss[115] - ss[114]);
    dens = fminf(fmaxf(dens, lo), hi);

    sd[g] = dens;
    __syncthreads();
    if (g == 0) {
        float m = 0.0f;
        for (int i = 0; i < 128; i++) m += sd[i];
        red = m / 128.0f;
    }
    __syncthreads();
    dens = 0.1f * dens / red;

    // centroid-of-centroids: thread g owns dim d = g
    float coc = 0.0f;
    for (int j = 0; j < 128; j++) coc += g_csum[j * 128 + g] / scnt[j];
    scoc[g] = coc * (1.0f / 128.0f);
    __syncthreads();

    float dot = 0.0f;
    for (int d = 0; d < 128; d++) dot += g_csum[g * 128 + d] * scoc[d];
    dot /= cnt2;

    float sim = expf(dot / dens);
    sd[g] = sim;
    __syncthreads();
    if (g == 0) {
        float m = sd[0], sum = 0.0f;
        for (int i = 0; i < 128; i++) {
            m = fmaxf(m, sd[i]);
            sum += sd[i];
        }
        // -mean(sim - max) = max - mean
        out[0] = m - sum / 128.0f;
    }
}

extern "C" void kernel_launch(void* const* d_in, const int* in_sizes, int n_in,
                              void* d_out, int out_size) {
    const float* X       = (const float*)d_in[0];
    const int*   subject = (const int*)d_in[1];
    const int*   labels  = (const int*)d_in[2];
    float*       out     = (float*)d_out;

    k_zero<<<64, 256>>>();
    k_hist<<<B_ROWS / 256, 256>>>(subject, labels);
    k_scan<<<1, 32>>>();
    k_scatter<<<B_ROWS / 256, 256>>>(subject, labels);
    k_centroid<<<G_NUM * CHUNKS, 256>>>(X);
    k_dist<<<G_NUM * CHUNKS, 256>>>(X);
    k_final<<<1, 128>>>(out);
}

// round 10
// speedup vs baseline: 1.2429x; 1.2429x over previous
#include <cuda_runtime.h>

#define B_ROWS 131072
#define D_DIM 128
#define G_NUM 128
#define CHUNKS 8

__device__ int   g_counts[G_NUM * 32];
__device__ int   g_cursor[G_NUM * 32];
__device__ int   g_offsets[G_NUM + 1];
__device__ int   g_bucket[B_ROWS];
__device__ float g_csum[G_NUM * D_DIM];
__device__ float g_dsum[G_NUM * 32];

__global__ void k_zero() {
    int i = blockIdx.x * blockDim.x + threadIdx.x;
    if (i < G_NUM * 32) { g_counts[i] = 0; g_dsum[i] = 0.0f; }
    if (i < G_NUM * D_DIM) g_csum[i] = 0.0f;
}

// Block-local smem histogram, then 128 global atomics per block.
__global__ void k_hist(const int* __restrict__ subject, const int* __restrict__ labels) {
    __shared__ int sc[G_NUM];
    int t = threadIdx.x;
    if (t < G_NUM) sc[t] = 0;
    __syncthreads();
    int base = blockIdx.x * 1024;
    #pragma unroll
    for (int k = 0; k < 4; k++) {
        int i = base + k * 256 + t;
        int g = subject[i] * 8 + labels[i];
        atomicAdd(&sc[g], 1);
    }
    __syncthreads();
    if (t < G_NUM && sc[t] > 0) atomicAdd(&g_counts[t * 32], sc[t]);
}

__global__ void k_scan() {
    if (threadIdx.x == 0) {
        int acc = 0;
        for (int g = 0; g < G_NUM; g++) {
            g_offsets[g] = acc;
            g_cursor[g * 32] = acc;
            acc += g_counts[g * 32];
        }
        g_offsets[G_NUM] = acc;
    }
}

// Block-aggregated scatter: local rank via smem atomics, one global
// reservation per (block, group).
__global__ void k_scatter(const int* __restrict__ subject, const int* __restrict__ labels) {
    __shared__ int scnt[G_NUM], sbase[G_NUM];
    int t = threadIdx.x;
    if (t < G_NUM) scnt[t] = 0;
    __syncthreads();
    int i = blockIdx.x * 256 + t;
    int g = subject[i] * 8 + labels[i];
    int local = atomicAdd(&scnt[g], 1);
    __syncthreads();
    if (t < G_NUM && scnt[t] > 0) sbase[t] = atomicAdd(&g_cursor[t * 32], scnt[t]);
    __syncthreads();
    g_bucket[sbase[g] + local] = i;
}

// Warp-per-row, lane l owns float4 dims 4l..4l+3 (views fold together).
// 2 rows per iteration -> 4 LDG.128 (2 KB) in flight per warp.
__global__ void k_centroid(const float* __restrict__ X) {
    int g = blockIdx.x >> 3, chunk = blockIdx.x & 7;
    int s0 = g_offsets[g], s1 = g_offsets[g + 1], n = s1 - s0;
    int cs = s0 + (n * chunk) / CHUNKS;
    int ce = s0 + (n * (chunk + 1)) / CHUNKS;
    int t = threadIdx.x, w = t >> 5, l = t & 31;

    float4 acc = make_float4(0.f, 0.f, 0.f, 0.f);
    int r = cs + w;
    for (; r + 8 < ce; r += 16) {
        int ba = g_bucket[r], bb = g_bucket[r + 8];
        const float4* pa = (const float4*)(X + (size_t)ba * 256);
        const float4* pb = (const float4*)(X + (size_t)bb * 256);
        float4 a0 = pa[l], a1 = pa[l + 32];
        float4 b0 = pb[l], b1 = pb[l + 32];
        acc.x += (a0.x + a1.x) + (b0.x + b1.x);
        acc.y += (a0.y + a1.y) + (b0.y + b1.y);
        acc.z += (a0.z + a1.z) + (b0.z + b1.z);
        acc.w += (a0.w + a1.w) + (b0.w + b1.w);
    }
    if (r < ce) {
        int b = g_bucket[r];
        const float4* p = (const float4*)(X + (size_t)b * 256);
        float4 a0 = p[l], a1 = p[l + 32];
        acc.x += a0.x + a1.x;
        acc.y += a0.y + a1.y;
        acc.z += a0.z + a1.z;
        acc.w += a0.w + a1.w;
    }

    __shared__ float4 sm[8][32];
    sm[w][l] = acc;
    __syncthreads();
    if (w == 0) {
        float4 tot = sm[0][l];
        #pragma unroll
        for (int i = 1; i < 8; i++) {
            float4 v = sm[i][l];
            tot.x += v.x; tot.y += v.y; tot.z += v.z; tot.w += v.w;
        }
        float* dst = &g_csum[g * 128 + 4 * l];
        atomicAdd(dst + 0, tot.x);
        atomicAdd(dst + 1, tot.y);
        atomicAdd(dst + 2, tot.z);
        atomicAdd(dst + 3, tot.w);
    }
}

__device__ __forceinline__ float sqdist(float4 a, float4 c) {
    float dx = a.x - c.x, dy = a.y - c.y, dz = a.z - c.z, dw = a.w - c.w;
    return dx * dx + dy * dy + dz * dz + dw * dw;
}

// Warp-per-row distances, traversed in REVERSE of k_centroid's order
// (mirrored block id + back-to-front rows) so the tail of the first pass —
// still resident in the 126 MB L2 — is reused first (LRU-friendly).
// 4 rows per iteration -> 8 LDG.128 (4 KB) in flight per warp.
__global__ void k_dist(const float* __restrict__ X) {
    int bid = (G_NUM * CHUNKS - 1) - blockIdx.x;  // mirror schedule order
    int g = bid >> 3, chunk = bid & 7;
    __shared__ float c[128];
    int t = threadIdx.x;
    float cnt2 = 2.0f * (float)g_counts[g * 32];
    if (t < 128) c[t] = g_csum[g * 128 + t] / cnt2;
    __syncthreads();

    int w = t >> 5, l = t & 31;
    float4 c4 = ((const float4*)c)[l];
    int s0 = g_offsets[g], s1 = g_offsets[g + 1], n = s1 - s0;
    int cs = s0 + (n * chunk) / CHUNKS;
    int ce = s0 + (n * (chunk + 1)) / CHUNKS;
    int mir = cs + ce - 1;  // row index mirror: r -> mir - r

    float s = 0.0f;
    int r = cs + w;
    for (; r + 24 < ce; r += 32) {
        int b0 = g_bucket[mir - r],        b1 = g_bucket[mir - (r + 8)];
        int b2 = g_bucket[mir - (r + 16)], b3 = g_bucket[mir - (r + 24)];
        const float4* p0 = (const float4*)(X + (size_t)b0 * 256);
        const float4* p1 = (const float4*)(X + (size_t)b1 * 256);
        const float4* p2 = (const float4*)(X + (size_t)b2 * 256);
        const float4* p3 = (const float4*)(X + (size_t)b3 * 256);
        float d[8];
        d[0] = sqdist(p0[l], c4);      d[1] = sqdist(p0[l + 32], c4);
        d[2] = sqdist(p1[l], c4);      d[3] = sqdist(p1[l + 32], c4);
        d[4] = sqdist(p2[l], c4);      d[5] = sqdist(p2[l + 32], c4);
        d[6] = sqdist(p3[l], c4);      d[7] = sqdist(p3[l + 32], c4);
        #pragma unroll
        for (int o = 16; o; o >>= 1) {
            #pragma unroll
            for (int k = 0; k < 8; k++) d[k] += __shfl_xor_sync(0xffffffff, d[k], o);
        }
        float sa = 0.0f;
        #pragma unroll
        for (int k = 0; k < 8; k++) sa += sqrtf(sqrtf(d[k]));
        s += sa;
    }
    for (; r + 8 < ce; r += 16) {
        int b0 = g_bucket[mir - r], b1 = g_bucket[mir - (r + 8)];
        const float4* p0 = (const float4*)(X + (size_t)b0 * 256);
        const float4* p1 = (const float4*)(X + (size_t)b1 * 256);
        float d[4];
        d[0] = sqdist(p0[l], c4); d[1] = sqdist(p0[l + 32], c4);
        d[2] = sqdist(p1[l], c4); d[3] = sqdist(p1[l + 32], c4);
        #pragma unroll
        for (int o = 16; o; o >>= 1) {
            #pragma unroll
            for (int k = 0; k < 4; k++) d[k] += __shfl_xor_sync(0xffffffff, d[k], o);
        }
        s += (sqrtf(sqrtf(d[0])) + sqrtf(sqrtf(d[1]))) + (sqrtf(sqrtf(d[2])) + sqrtf(sqrtf(d[3])));
    }
    if (r < ce) {
        int b = g_bucket[mir - r];
        const float4* p = (const float4*)(X + (size_t)b * 256);
        float d0 = sqdist(p[l], c4), d1 = sqdist(p[l + 32], c4);
        #pragma unroll
        for (int o = 16; o; o >>= 1) {
            d0 += __shfl_xor_sync(0xffffffff, d0, o);
            d1 += __shfl_xor_sync(0xffffffff, d1, o);
        }
        s += sqrtf(sqrtf(d0)) + sqrtf(sqrtf(d1));
    }
    if (l == 0) atomicAdd(&g_dsum[g * 32], s);
}

__global__ void k_final(float* __restrict__ out) {
    int g = threadIdx.x;
    __shared__ float sd[128], ss[128], scnt[128], scoc[128];
    __shared__ float red;

    float cnt2 = 2.0f * (float)g_counts[g * 32];
    scnt[g] = cnt2;
    float dens = (g_dsum[g * 32] / cnt2) / logf(cnt2 + 10.0f);
    bool valid = cnt2 > 1.0f;
    sd[g] = valid ? dens : 0.0f;
    __syncthreads();
    if (g == 0) {
        float m = sd[0];
        for (int i = 1; i < 128; i++) m = fmaxf(m, sd[i]);
        red = m;
    }
    __syncthreads();
    dens = valid ? dens : red;

    sd[g] = dens;
    __syncthreads();
    int rank = 0;
    for (int j = 0; j < 128; j++) {
        float v = sd[j];
        rank += (v < dens) || (v == dens && j < g);
    }
    ss[rank] = dens;
    __syncthreads();
    float lo = ss[12] + 0.7f * (ss[13] - ss[12]);
    float hi = ss[114] + 0.3f * (ss[115] - ss[114]);
    dens = fminf(fmaxf(dens, lo), hi);

    sd[g] = dens;
    __syncthreads();
    if (g == 0) {
        float m = 0.0f;
        for (int i = 0; i < 128; i++) m += sd[i];
        red = m / 128.0f;
    }
    __syncthreads();
    dens = 0.1f * dens / red;

    float coc = 0.0f;
    for (int j = 0; j < 128; j++) coc += g_csum[j * 128 + g] / scnt[j];
    scoc[g] = coc * (1.0f / 128.0f);
    __syncthreads();

    float dot = 0.0f;
    for (int d = 0; d < 128; d++) dot += g_csum[g * 128 + d] * scoc[d];
    dot /= cnt2;

    float sim = expf(dot / dens);
    sd[g] = sim;
    __syncthreads();
    if (g == 0) {
        float m = sd[0], sum = 0.0f;
        for (int i = 0; i < 128; i++) {
            m = fmaxf(m, sd[i]);
            sum += sd[i];
        }
        out[0] = m - sum / 128.0f;
    }
}

extern "C" void kernel_launch(void* const* d_in, const int* in_sizes, int n_in,
                              void* d_out, int out_size) {
    const float* X       = (const float*)d_in[0];
    const int*   subject = (const int*)d_in[1];
    const int*   labels  = (const int*)d_in[2];
    float*       out     = (float*)d_out;

    k_zero<<<64, 256>>>();
    k_hist<<<B_ROWS / 1024, 256>>>(subject, labels);
    k_scan<<<1, 32>>>();
    k_scatter<<<B_ROWS / 256, 256>>>(subject, labels);
    k_centroid<<<G_NUM * CHUNKS, 256>>>(X);
    k_dist<<<G_NUM * CHUNKS, 256>>>(X);
    k_final<<<1, 128>>>(out);
}

// round 12
// speedup vs baseline: 1.6754x; 1.3479x over previous
#include <cuda_runtime.h>

#define B_ROWS 131072
#define D_DIM 128
#define G_NUM 128
#define CHUNKS 8
#define HBLOCKS 128

__device__ int   g_part[HBLOCKS * G_NUM];
__device__ int   g_counts[G_NUM * 32];
__device__ int   g_cursor[G_NUM * 32];
__device__ int   g_offsets[G_NUM + 1];
__device__ int   g_bucket[B_ROWS];
__device__ float g_csum[G_NUM * D_DIM];
__device__ float g_dsum[G_NUM * 32];

// Atomic-free histogram: block-local smem counts -> private g_part slice.
__global__ void k_hist(const int* __restrict__ subject, const int* __restrict__ labels) {
    __shared__ int sc[G_NUM];
    int t = threadIdx.x;
    if (t < G_NUM) sc[t] = 0;
    __syncthreads();
    int base = blockIdx.x * 1024;
    #pragma unroll
    for (int k = 0; k < 4; k++) {
        int i = base + k * 256 + t;
        int g = subject[i] * 8 + labels[i];
        atomicAdd(&sc[g], 1);
    }
    __syncthreads();
    if (t < G_NUM) g_part[blockIdx.x * G_NUM + t] = sc[t];
}

// One block, 128 threads: reduce partials, parallel exclusive scan,
// and zero csum/dsum (replaces the old k_zero + serial k_scan).
__global__ void k_scan() {
    int t = threadIdx.x;
    int cnt = 0;
    for (int b = 0; b < HBLOCKS; b++) cnt += g_part[b * G_NUM + t];
    g_counts[t * 32] = cnt;

    int lane = t & 31, wid = t >> 5;
    int incl = cnt;
    #pragma unroll
    for (int o = 1; o < 32; o <<= 1) {
        int v = __shfl_up_sync(0xffffffff, incl, o);
        if (lane >= o) incl += v;
    }
    __shared__ int wsum[4];
    if (lane == 31) wsum[wid] = incl;
    __syncthreads();
    int base = 0;
    for (int i = 0; i < wid; i++) base += wsum[i];
    int excl = base + incl - cnt;
    g_offsets[t] = excl;
    g_cursor[t * 32] = excl;
    if (t == G_NUM - 1) g_offsets[G_NUM] = excl + cnt;

    // zero accumulators
    float4* cz = (float4*)g_csum;
    for (int i = t; i < G_NUM * D_DIM / 4; i += 128)
        cz[i] = make_float4(0.f, 0.f, 0.f, 0.f);
    g_dsum[t * 32] = 0.0f;
}

// Block-aggregated scatter: 1024 threads/block -> 128 blocks, one wave,
// 4x fewer global atomic reservation rounds.
__global__ void k_scatter(const int* __restrict__ subject, const int* __restrict__ labels) {
    __shared__ int scnt[G_NUM], sbase[G_NUM];
    int t = threadIdx.x;
    if (t < G_NUM) scnt[t] = 0;
    __syncthreads();
    int i = blockIdx.x * 1024 + t;
    int g = subject[i] * 8 + labels[i];
    int local = atomicAdd(&scnt[g], 1);
    __syncthreads();
    if (t < G_NUM && scnt[t] > 0) sbase[t] = atomicAdd(&g_cursor[t * 32], scnt[t]);
    __syncthreads();
    g_bucket[sbase[g] + local] = i;
}

// Warp-per-row centroid sums: 4 rows/iter -> 8 LDG.128 (4 KB) in flight.
__global__ void k_centroid(const float* __restrict__ X) {
    int g = blockIdx.x >> 3, chunk = blockIdx.x & 7;
    int s0 = g_offsets[g], s1 = g_offsets[g + 1], n = s1 - s0;
    int cs = s0 + (n * chunk) / CHUNKS;
    int ce = s0 + (n * (chunk + 1)) / CHUNKS;
    int t = threadIdx.x, w = t >> 5, l = t & 31;

    float4 acc = make_float4(0.f, 0.f, 0.f, 0.f);
    int r = cs + w;
    for (; r + 24 < ce; r += 32) {
        int b0 = g_bucket[r],      b1 = g_bucket[r + 8];
        int b2 = g_bucket[r + 16], b3 = g_bucket[r + 24];
        const float4* p0 = (const float4*)(X + (size_t)b0 * 256);
        const float4* p1 = (const float4*)(X + (size_t)b1 * 256);
        const float4* p2 = (const float4*)(X + (size_t)b2 * 256);
        const float4* p3 = (const float4*)(X + (size_t)b3 * 256);
        float4 a0 = p0[l], a1 = p0[l + 32];
        float4 b0v = p1[l], b1v = p1[l + 32];
        float4 c0 = p2[l], c1 = p2[l + 32];
        float4 d0 = p3[l], d1 = p3[l + 32];
        acc.x += ((a0.x + a1.x) + (b0v.x + b1v.x)) + ((c0.x + c1.x) + (d0.x + d1.x));
        acc.y += ((a0.y + a1.y) + (b0v.y + b1v.y)) + ((c0.y + c1.y) + (d0.y + d1.y));
        acc.z += ((a0.z + a1.z) + (b0v.z + b1v.z)) + ((c0.z + c1.z) + (d0.z + d1.z));
        acc.w += ((a0.w + a1.w) + (b0v.w + b1v.w)) + ((c0.w + c1.w) + (d0.w + d1.w));
    }
    for (; r + 8 < ce; r += 16) {
        int b0 = g_bucket[r], b1 = g_bucket[r + 8];
        const float4* pa = (const float4*)(X + (size_t)b0 * 256);
        const float4* pb = (const float4*)(X + (size_t)b1 * 256);
        float4 a0 = pa[l], a1 = pa[l + 32];
        float4 b0v = pb[l], b1v = pb[l + 32];
        acc.x += (a0.x + a1.x) + (b0v.x + b1v.x);
        acc.y += (a0.y + a1.y) + (b0v.y + b1v.y);
        acc.z += (a0.z + a1.z) + (b0v.z + b1v.z);
        acc.w += (a0.w + a1.w) + (b0v.w + b1v.w);
    }
    if (r < ce) {
        int b = g_bucket[r];
        const float4* p = (const float4*)(X + (size_t)b * 256);
        float4 a0 = p[l], a1 = p[l + 32];
        acc.x += a0.x + a1.x;
        acc.y += a0.y + a1.y;
        acc.z += a0.z + a1.z;
        acc.w += a0.w + a1.w;
    }

    __shared__ float4 sm[8][32];
    sm[w][l] = acc;
    __syncthreads();
    if (w == 0) {
        float4 tot = sm[0][l];
        #pragma unroll
        for (int i = 1; i < 8; i++) {
            float4 v = sm[i][l];
            tot.x += v.x; tot.y += v.y; tot.z += v.z; tot.w += v.w;
        }
        float* dst = &g_csum[g * 128 + 4 * l];
        atomicAdd(dst + 0, tot.x);
        atomicAdd(dst + 1, tot.y);
        atomicAdd(dst + 2, tot.z);
        atomicAdd(dst + 3, tot.w);
    }
}

__device__ __forceinline__ float sqdist(float4 a, float4 c) {
    float dx = a.x - c.x, dy = a.y - c.y, dz = a.z - c.z, dw = a.w - c.w;
    return dx * dx + dy * dy + dz * dz + dw * dw;
}

// Warp-per-row distances, traversed in REVERSE of k_centroid's order
// so the L2-resident tail of pass 1 is reused first.
__global__ void k_dist(const float* __restrict__ X) {
    int bid = (G_NUM * CHUNKS - 1) - blockIdx.x;
    int g = bid >> 3, chunk = bid & 7;
    __shared__ float c[128];
    int t = threadIdx.x;
    float cnt2 = 2.0f * (float)g_counts[g * 32];
    if (t < 128) c[t] = g_csum[g * 128 + t] / cnt2;
    __syncthreads();

    int w = t >> 5, l = t & 31;
    float4 c4 = ((const float4*)c)[l];
    int s0 = g_offsets[g], s1 = g_offsets[g + 1], n = s1 - s0;
    int cs = s0 + (n * chunk) / CHUNKS;
    int ce = s0 + (n * (chunk + 1)) / CHUNKS;
    int mir = cs + ce - 1;

    float s = 0.0f;
    int r = cs + w;
    for (; r + 24 < ce; r += 32) {
        int b0 = g_bucket[mir - r],        b1 = g_bucket[mir - (r + 8)];
        int b2 = g_bucket[mir - (r + 16)], b3 = g_bucket[mir - (r + 24)];
        const float4* p0 = (const float4*)(X + (size_t)b0 * 256);
        const float4* p1 = (const float4*)(X + (size_t)b1 * 256);
        const float4* p2 = (const float4*)(X + (size_t)b2 * 256);
        const float4* p3 = (const float4*)(X + (size_t)b3 * 256);
        float d[8];
        d[0] = sqdist(p0[l], c4);      d[1] = sqdist(p0[l + 32], c4);
        d[2] = sqdist(p1[l], c4);      d[3] = sqdist(p1[l + 32], c4);
        d[4] = sqdist(p2[l], c4);      d[5] = sqdist(p2[l + 32], c4);
        d[6] = sqdist(p3[l], c4);      d[7] = sqdist(p3[l + 32], c4);
        #pragma unroll
        for (int o = 16; o; o >>= 1) {
            #pragma unroll
            for (int k = 0; k < 8; k++) d[k] += __shfl_xor_sync(0xffffffff, d[k], o);
        }
        float sa = 0.0f;
        #pragma unroll
        for (int k = 0; k < 8; k++) sa += sqrtf(sqrtf(d[k]));
        s += sa;
    }
    for (; r + 8 < ce; r += 16) {
        int b0 = g_bucket[mir - r], b1 = g_bucket[mir - (r + 8)];
        const float4* p0 = (const float4*)(X + (size_t)b0 * 256);
        const float4* p1 = (const float4*)(X + (size_t)b1 * 256);
        float d[4];
        d[0] = sqdist(p0[l], c4); d[1] = sqdist(p0[l + 32], c4);
        d[2] = sqdist(p1[l], c4); d[3] = sqdist(p1[l + 32], c4);
        #pragma unroll
        for (int o = 16; o; o >>= 1) {
            #pragma unroll
            for (int k = 0; k < 4; k++) d[k] += __shfl_xor_sync(0xffffffff, d[k], o);
        }
        s += (sqrtf(sqrtf(d[0])) + sqrtf(sqrtf(d[1]))) + (sqrtf(sqrtf(d[2])) + sqrtf(sqrtf(d[3])));
    }
    if (r < ce) {
        int b = g_bucket[mir - r];
        const float4* p = (const float4*)(X + (size_t)b * 256);
        float d0 = sqdist(p[l], c4), d1 = sqdist(p[l + 32], c4);
        #pragma unroll
        for (int o = 16; o; o >>= 1) {
            d0 += __shfl_xor_sync(0xffffffff, d0, o);
            d1 += __shfl_xor_sync(0xffffffff, d1, o);
        }
        s += sqrtf(sqrtf(d0)) + sqrtf(sqrtf(d1));
    }
    if (l == 0) atomicAdd(&g_dsum[g * 32], s);
}

__global__ void k_final(float* __restrict__ out) {
    int g = threadIdx.x;
    __shared__ float sd[128], ss[128], scnt[128], scoc[128], sdot[128];
    __shared__ float red;

    float cnt2 = 2.0f * (float)g_counts[g * 32];
    scnt[g] = cnt2;
    float dens = (g_dsum[g * 32] / cnt2) / logf(cnt2 + 10.0f);
    bool valid = cnt2 > 1.0f;
    sd[g] = valid ? dens : 0.0f;
    __syncthreads();
    if (g == 0) {
        float m = sd[0];
        for (int i = 1; i < 128; i++) m = fmaxf(m, sd[i]);
        red = m;
    }
    __syncthreads();
    dens = valid ? dens : red;

    sd[g] = dens;
    __syncthreads();
    int rank = 0;
    for (int j = 0; j < 128; j++) {
        float v = sd[j];
        rank += (v < dens) || (v == dens && j < g);
    }
    ss[rank] = dens;
    __syncthreads();
    float lo = ss[12] + 0.7f * (ss[13] - ss[12]);
    float hi = ss[114] + 0.3f * (ss[115] - ss[114]);
    dens = fminf(fmaxf(dens, lo), hi);

    sd[g] = dens;
    __syncthreads();
    if (g == 0) {
        float m = 0.0f;
        for (int i = 0; i < 128; i++) m += sd[i];
        red = m / 128.0f;
    }
    __syncthreads();
    dens = 0.1f * dens / red;

    // centroid-of-centroids: thread g owns dim g (coalesced column reads)
    float coc = 0.0f;
    for (int j = 0; j < 128; j++) coc += g_csum[j * 128 + g] / scnt[j];
    scoc[g] = coc * (1.0f / 128.0f);
    __syncthreads();

    // dot_g = csum[g,:].scoc via per-row warp reduction (coalesced loads)
    {
        int lane = g & 31, wid = g >> 5;
        for (int j = wid; j < 128; j += 4) {
            const float* row = &g_csum[j * 128];
            float v = row[lane] * scoc[lane]
                    + row[lane + 32] * scoc[lane + 32]
                    + row[lane + 64] * scoc[lane + 64]
                    + row[lane + 96] * scoc[lane + 96];
            #pragma unroll
            for (int o = 16; o; o >>= 1) v += __shfl_xor_sync(0xffffffff, v, o);
            if (lane == 0) sdot[j] = v;
        }
    }
    __syncthreads();
    float dot = sdot[g] / cnt2;

    float sim = expf(dot / dens);
    sd[g] = sim;
    __syncthreads();
    if (g == 0) {
        float m = sd[0], sum = 0.0f;
        for (int i = 0; i < 128; i++) {
            m = fmaxf(m, sd[i]);
            sum += sd[i];
        }
        out[0] = m - sum / 128.0f;
    }
}

extern "C" void kernel_launch(void* const* d_in, const int* in_sizes, int n_in,
                              void* d_out, int out_size) {
    const float* X       = (const float*)d_in[0];
    const int*   subject = (const int*)d_in[1];
    const int*   labels  = (const int*)d_in[2];
    float*       out     = (float*)d_out;

    k_hist<<<HBLOCKS, 256>>>(subject, labels);
    k_scan<<<1, 128>>>();
    k_scatter<<<B_ROWS / 1024, 1024>>>(subject, labels);
    k_centroid<<<G_NUM * CHUNKS, 256>>>(X);
    k_dist<<<G_NUM * CHUNKS, 256>>>(X);
    k_final<<<1, 128>>>(out);
}

// round 13
// speedup vs baseline: 1.8695x; 1.1159x over previous
#include <cuda_runtime.h>

#define B_ROWS 131072
#define D_DIM 128
#define G_NUM 128
#define HBLOCKS 128
#define FBLOCKS 592   // 148 SMs x 4 blocks guaranteed co-resident

__device__ int   g_part[HBLOCKS * G_NUM];
__device__ int   g_counts[G_NUM * 32];
__device__ int   g_cursor[G_NUM * 32];
__device__ int   g_offsets[G_NUM + 1];
__device__ int   g_bucket[B_ROWS];
__device__ float g_csum[G_NUM * D_DIM];
__device__ float g_dsum[G_NUM * 32];
__device__ int   g_bar;

// Atomic-free histogram: block-local smem counts -> private g_part slice.
__global__ void k_hist(const int* __restrict__ subject, const int* __restrict__ labels) {
    __shared__ int sc[G_NUM];
    int t = threadIdx.x;
    if (t < G_NUM) sc[t] = 0;
    __syncthreads();
    int base = blockIdx.x * 1024;
    #pragma unroll
    for (int k = 0; k < 4; k++) {
        int i = base + k * 256 + t;
        int g = subject[i] * 8 + labels[i];
        atomicAdd(&sc[g], 1);
    }
    __syncthreads();
    if (t < G_NUM) g_part[blockIdx.x * G_NUM + t] = sc[t];
}

// Reduce partials, parallel exclusive scan, zero accumulators + barrier.
__global__ void k_scan() {
    int t = threadIdx.x;
    int cnt = 0;
    for (int b = 0; b < HBLOCKS; b++) cnt += g_part[b * G_NUM + t];
    g_counts[t * 32] = cnt;

    int lane = t & 31, wid = t >> 5;
    int incl = cnt;
    #pragma unroll
    for (int o = 1; o < 32; o <<= 1) {
        int v = __shfl_up_sync(0xffffffff, incl, o);
        if (lane >= o) incl += v;
    }
    __shared__ int wsum[4];
    if (lane == 31) wsum[wid] = incl;
    __syncthreads();
    int base = 0;
    for (int i = 0; i < wid; i++) base += wsum[i];
    int excl = base + incl - cnt;
    g_offsets[t] = excl;
    g_cursor[t * 32] = excl;
    if (t == G_NUM - 1) g_offsets[G_NUM] = excl + cnt;
    if (t == 0) g_bar = 0;

    float4* cz = (float4*)g_csum;
    for (int i = t; i < G_NUM * D_DIM / 4; i += 128)
        cz[i] = make_float4(0.f, 0.f, 0.f, 0.f);
    g_dsum[t * 32] = 0.0f;
}

// Block-aggregated scatter: 1024 threads/block, one wave.
__global__ void k_scatter(const int* __restrict__ subject, const int* __restrict__ labels) {
    __shared__ int scnt[G_NUM], sbase[G_NUM];
    int t = threadIdx.x;
    if (t < G_NUM) scnt[t] = 0;
    __syncthreads();
    int i = blockIdx.x * 1024 + t;
    int g = subject[i] * 8 + labels[i];
    int local = atomicAdd(&scnt[g], 1);
    __syncthreads();
    if (t < G_NUM && scnt[t] > 0) sbase[t] = atomicAdd(&g_cursor[t * 32], scnt[t]);
    __syncthreads();
    g_bucket[sbase[g] + local] = i;
}

__device__ __forceinline__ int find_group(int row) {
    int lo = 0, hi = G_NUM;
    while (hi - lo > 1) {
        int mid = (lo + hi) >> 1;
        if (g_offsets[mid] <= row) lo = mid; else hi = mid;
    }
    return lo;
}

// Software grid barrier: all FBLOCKS blocks are co-resident by launch_bounds.
__device__ __forceinline__ void grid_barrier(int target) {
    __threadfence();
    __syncthreads();
    if (threadIdx.x == 0) {
        atomicAdd(&g_bar, 1);
        while (*(volatile int*)&g_bar < target) { }
    }
    __syncthreads();
}

__device__ __forceinline__ float sqdist(float4 a, float4 c) {
    float dx = a.x - c.x, dy = a.y - c.y, dz = a.z - c.z, dw = a.w - c.w;
    return dx * dx + dy * dy + dz * dz + dw * dw;
}

// Fused centroid + distance: persistent blocks over contiguous row ranges
// (perfect load balance, zero wave tail), global barrier between phases,
// mirrored ranges in phase B for L2 reuse.
__global__ void __launch_bounds__(256, 4) k_fused(const float* __restrict__ X) {
    int b = blockIdx.x, t = threadIdx.x, w = t >> 5, l = t & 31;
    __shared__ float4 sm[8][32];
    __shared__ float c[128];

    // ---- Phase A: centroid partial sums ----
    {
        int rs = (int)((long long)b * B_ROWS / FBLOCKS);
        int re = (int)((long long)(b + 1) * B_ROWS / FBLOCKS);
        int g = find_group(rs);
        while (rs < re) {
            int se = min(re, g_offsets[g + 1]);
            float4 acc = make_float4(0.f, 0.f, 0.f, 0.f);
            int r = rs + w;
            for (; r + 24 < se; r += 32) {
                int b0 = g_bucket[r],      b1 = g_bucket[r + 8];
                int b2 = g_bucket[r + 16], b3 = g_bucket[r + 24];
                const float4* p0 = (const float4*)(X + (size_t)b0 * 256);
                const float4* p1 = (const float4*)(X + (size_t)b1 * 256);
                const float4* p2 = (const float4*)(X + (size_t)b2 * 256);
                const float4* p3 = (const float4*)(X + (size_t)b3 * 256);
                float4 a0 = p0[l], a1 = p0[l + 32];
                float4 b0v = p1[l], b1v = p1[l + 32];
                float4 c0 = p2[l], c1 = p2[l + 32];
                float4 d0 = p3[l], d1 = p3[l + 32];
                acc.x += ((a0.x + a1.x) + (b0v.x + b1v.x)) + ((c0.x + c1.x) + (d0.x + d1.x));
                acc.y += ((a0.y + a1.y) + (b0v.y + b1v.y)) + ((c0.y + c1.y) + (d0.y + d1.y));
                acc.z += ((a0.z + a1.z) + (b0v.z + b1v.z)) + ((c0.z + c1.z) + (d0.z + d1.z));
                acc.w += ((a0.w + a1.w) + (b0v.w + b1v.w)) + ((c0.w + c1.w) + (d0.w + d1.w));
            }
            for (; r < se; r += 8) {
                int bb = g_bucket[r];
                const float4* p = (const float4*)(X + (size_t)bb * 256);
                float4 a0 = p[l], a1 = p[l + 32];
                acc.x += a0.x + a1.x;
                acc.y += a0.y + a1.y;
                acc.z += a0.z + a1.z;
                acc.w += a0.w + a1.w;
            }
            sm[w][l] = acc;
            __syncthreads();
            if (w == 0) {
                float4 tot = sm[0][l];
                #pragma unroll
                for (int i = 1; i < 8; i++) {
                    float4 v = sm[i][l];
                    tot.x += v.x; tot.y += v.y; tot.z += v.z; tot.w += v.w;
                }
                float* dst = &g_csum[g * 128 + 4 * l];
                atomicAdd(dst + 0, tot.x);
                atomicAdd(dst + 1, tot.y);
                atomicAdd(dst + 2, tot.z);
                atomicAdd(dst + 3, tot.w);
            }
            __syncthreads();
            rs = se; g++;
        }
    }

    grid_barrier(FBLOCKS);

    // ---- Phase B: distances (mirrored block range for L2 reuse) ----
    {
        int mb = FBLOCKS - 1 - b;
        int rs = (int)((long long)mb * B_ROWS / FBLOCKS);
        int re = (int)((long long)(mb + 1) * B_ROWS / FBLOCKS);
        int g = find_group(rs);
        while (rs < re) {
            int se = min(re, g_offsets[g + 1]);
            float cnt2 = 2.0f * (float)g_counts[g * 32];
            if (t < 128) c[t] = __ldcg(&g_csum[g * 128 + t]) / cnt2;
            __syncthreads();
            float4 c4 = ((const float4*)c)[l];
            float s = 0.0f;
            int r = rs + w;
            for (; r + 24 < se; r += 32) {
                int b0 = g_bucket[r],      b1 = g_bucket[r + 8];
                int b2 = g_bucket[r + 16], b3 = g_bucket[r + 24];
                const float4* p0 = (const float4*)(X + (size_t)b0 * 256);
                const float4* p1 = (const float4*)(X + (size_t)b1 * 256);
                const float4* p2 = (const float4*)(X + (size_t)b2 * 256);
                const float4* p3 = (const float4*)(X + (size_t)b3 * 256);
                float d[8];
                d[0] = sqdist(p0[l], c4);      d[1] = sqdist(p0[l + 32], c4);
                d[2] = sqdist(p1[l], c4);      d[3] = sqdist(p1[l + 32], c4);
                d[4] = sqdist(p2[l], c4);      d[5] = sqdist(p2[l + 32], c4);
                d[6] = sqdist(p3[l], c4);      d[7] = sqdist(p3[l + 32], c4);
                #pragma unroll
                for (int o = 16; o; o >>= 1) {
                    #pragma unroll
                    for (int k = 0; k < 8; k++) d[k] += __shfl_xor_sync(0xffffffff, d[k], o);
                }
                float sa = 0.0f;
                #pragma unroll
                for (int k = 0; k < 8; k++) sa += sqrtf(sqrtf(d[k]));
                s += sa;
            }
            for (; r < se; r += 8) {
                int bb = g_bucket[r];
                const float4* p = (const float4*)(X + (size_t)bb * 256);
                float d0 = sqdist(p[l], c4), d1 = sqdist(p[l + 32], c4);
                #pragma unroll
                for (int o = 16; o; o >>= 1) {
                    d0 += __shfl_xor_sync(0xffffffff, d0, o);
                    d1 += __shfl_xor_sync(0xffffffff, d1, o);
                }
                s += sqrtf(sqrtf(d0)) + sqrtf(sqrtf(d1));
            }
            if (l == 0) atomicAdd(&g_dsum[g * 32], s);
            __syncthreads();
            rs = se; g++;
        }
    }
}

__global__ void k_final(float* __restrict__ out) {
    int g = threadIdx.x;
    __shared__ float sd[128], ss[128], scnt[128], scoc[128], sdot[128];
    __shared__ float red;

    float cnt2 = 2.0f * (float)g_counts[g * 32];
    scnt[g] = cnt2;
    float dens = (g_dsum[g * 32] / cnt2) / logf(cnt2 + 10.0f);
    bool valid = cnt2 > 1.0f;
    sd[g] = valid ? dens : 0.0f;
    __syncthreads();
    if (g == 0) {
        float m = sd[0];
        for (int i = 1; i < 128; i++) m = fmaxf(m, sd[i]);
        red = m;
    }
    __syncthreads();
    dens = valid ? dens : red;

    sd[g] = dens;
    __syncthreads();
    int rank = 0;
    for (int j = 0; j < 128; j++) {
        float v = sd[j];
        rank += (v < dens) || (v == dens && j < g);
    }
    ss[rank] = dens;
    __syncthreads();
    float lo = ss[12] + 0.7f * (ss[13] - ss[12]);
    float hi = ss[114] + 0.3f * (ss[115] - ss[114]);
    dens = fminf(fmaxf(dens, lo), hi);

    sd[g] = dens;
    __syncthreads();
    if (g == 0) {
        float m = 0.0f;
        for (int i = 0; i < 128; i++) m += sd[i];
        red = m / 128.0f;
    }
    __syncthreads();
    dens = 0.1f * dens / red;

    float coc = 0.0f;
    for (int j = 0; j < 128; j++) coc += g_csum[j * 128 + g] / scnt[j];
    scoc[g] = coc * (1.0f / 128.0f);
    __syncthreads();

    {
        int lane = g & 31, wid = g >> 5;
        for (int j = wid; j < 128; j += 4) {
            const float* row = &g_csum[j * 128];
            float v = row[lane] * scoc[lane]
                    + row[lane + 32] * scoc[lane + 32]
                    + row[lane + 64] * scoc[lane + 64]
                    + row[lane + 96] * scoc[lane + 96];
            #pragma unroll
            for (int o = 16; o; o >>= 1) v += __shfl_xor_sync(0xffffffff, v, o);
            if (lane == 0) sdot[j] = v;
        }
    }
    __syncthreads();
    float dot = sdot[g] / cnt2;

    float sim = expf(dot / dens);
    sd[g] = sim;
    __syncthreads();
    if (g == 0) {
        float m = sd[0], sum = 0.0f;
        for (int i = 0; i < 128; i++) {
            m = fmaxf(m, sd[i]);
            sum += sd[i];
        }
        out[0] = m - sum / 128.0f;
    }
}

extern "C" void kernel_launch(void* const* d_in, const int* in_sizes, int n_in,
                              void* d_out, int out_size) {
    const float* X       = (const float*)d_in[0];
    const int*   subject = (const int*)d_in[1];
    const int*   labels  = (const int*)d_in[2];
    float*       out     = (float*)d_out;

    k_hist<<<HBLOCKS, 256>>>(subject, labels);
    k_scan<<<1, 128>>>();
    k_scatter<<<B_ROWS / 1024, 1024>>>(subject, labels);
    k_fused<<<FBLOCKS, 256>>>(X);
    k_final<<<1, 128>>>(out);
}